// round 1
// baseline (speedup 1.0000x reference)
#include <cuda_runtime.h>
#include <cuda_bf16.h>
#include <math.h>

// ---------------- Problem constants ----------------
#define T_TOK   1024
#define HDIM    1024
#define NEXP    64
#define TOPK    6
#define NGRP    8
#define TOPG    4
#define FDIM    512
#define FSH     1024      // F*NSH for shared experts
#define CAP     384
#define SCALE   2.5f

// ---------------- Device scratch (no allocs allowed) ----------------
__device__ float g_buf[NEXP * CAP * HDIM];    // dispatch buffer [E,CAP,H]   96MB
__device__ float g_act[NEXP * CAP * FDIM];    // silu-mul act    [E,CAP,F]   48MB
__device__ float g_eo [NEXP * CAP * HDIM];    // expert out      [E,CAP,H]   96MB
__device__ float g_acts[T_TOK * FSH];         // shared act      [T,FSH]      4MB
__device__ int   g_cnt[NEXP];
__device__ int   g_ids[T_TOK * TOPK];
__device__ int   g_pos[T_TOK * TOPK];
__device__ float g_wts[T_TOK * TOPK];

// ---------------- Gate + grouped top-k ----------------
// one block per token, 64 threads (one per expert)
__global__ void gate_topk_kernel(const float* __restrict__ x,
                                 const float* __restrict__ gw,
                                 const float* __restrict__ bias)
{
    __shared__ float xs[HDIM];
    __shared__ float scores[NEXP];
    __shared__ float sc[NEXP];

    int t = blockIdx.x;
    for (int i = threadIdx.x; i < HDIM; i += blockDim.x)
        xs[i] = x[(size_t)t * HDIM + i];
    __syncthreads();

    int e = threadIdx.x;  // 0..63
    const float* g = gw + (size_t)e * HDIM;
    float acc = 0.f;
    #pragma unroll 8
    for (int i = 0; i < HDIM; i++) acc = fmaf(xs[i], g[i], acc);
    float s = 1.f / (1.f + expf(-acc));
    scores[e] = s;
    sc[e]     = s + bias[e];
    __syncthreads();

    if (threadIdx.x == 0) {
        // group scores: sum of top-2 per group of 8
        float gs[NGRP];
        for (int gi = 0; gi < NGRP; gi++) {
            float m1 = -1e30f, m2 = -1e30f;
            for (int j = 0; j < 8; j++) {
                float v = sc[gi * 8 + j];
                if (v > m1) { m2 = m1; m1 = v; }
                else if (v > m2) { m2 = v; }
            }
            gs[gi] = m1 + m2;
        }
        // top-4 groups (strict > keeps lowest index on ties, like lax.top_k)
        bool gsel[NGRP];
        for (int gi = 0; gi < NGRP; gi++) gsel[gi] = false;
        for (int r = 0; r < TOPG; r++) {
            int bi = -1; float bv = -1e30f;
            for (int gi = 0; gi < NGRP; gi++)
                if (!gsel[gi] && gs[gi] > bv) { bv = gs[gi]; bi = gi; }
            gsel[bi] = true;
        }
        // masked top-6 experts
        float masked[NEXP];
        for (int i = 0; i < NEXP; i++)
            masked[i] = gsel[i >> 3] ? sc[i] : -1e30f;
        int   id[TOPK];
        float wsum = 0.f;
        for (int r = 0; r < TOPK; r++) {
            int bi = -1; float bv = -1e30f;
            for (int i = 0; i < NEXP; i++)
                if (masked[i] > bv) { bv = masked[i]; bi = i; }
            masked[bi] = -1e30f;
            id[r] = bi;
            wsum += scores[bi];
        }
        float inv = SCALE / wsum;
        for (int r = 0; r < TOPK; r++) {
            g_ids[t * TOPK + r] = id[r];
            g_wts[t * TOPK + r] = scores[id[r]] * inv;
        }
    }
}

// ---------------- Dispatch ----------------
__global__ void zero_cnt_kernel() {
    if (threadIdx.x < NEXP) g_cnt[threadIdx.x] = 0;
}

__global__ void assign_kernel() {
    int i = blockIdx.x * blockDim.x + threadIdx.x;
    if (i < T_TOK * TOPK) {
        int e = g_ids[i];
        int p = atomicAdd(&g_cnt[e], 1);
        g_pos[i] = p;
    }
}

// one block per (token, k) assignment: copy token row into expert buffer
__global__ void scatter_kernel(const float* __restrict__ x) {
    int i = blockIdx.x;            // 0..6143
    int p = g_pos[i];
    if (p >= CAP) return;
    int e = g_ids[i];
    int t = i / TOPK;
    const float4* src = (const float4*)(x + (size_t)t * HDIM);
    float4* dst = (float4*)(g_buf + ((size_t)e * CAP + p) * HDIM);
    for (int j = threadIdx.x; j < HDIM / 4; j += blockDim.x) dst[j] = src[j];
}

// ---------------- Fused GEMM13 + SiLU*Mul ----------------
// C[m, n] = silu(A@B[:, n]) * (A@B[:, n + halfOff])   for n in this expert's half
// grid: (ntiles, nexperts, mtiles); early-exit on per-expert count.
#define BM 64
#define BN 64
#define BK 16

__global__ __launch_bounds__(256)
void gemm13_kernel(const float* __restrict__ A0, int lda, size_t sAe,
                   const float* __restrict__ B0, int ldb, size_t sBe,
                   float* __restrict__ C0, int ldc, size_t sCe,
                   int halfOff, int Kdim, const int* __restrict__ cnt)
{
    int e = blockIdx.y;
    if (cnt) { if ((int)blockIdx.z * BM >= cnt[e]) return; }
    const float* A = A0 + (size_t)e * sAe + (size_t)blockIdx.z * BM * lda;
    const float* B = B0 + (size_t)e * sBe;
    float* C       = C0 + (size_t)e * sCe + (size_t)blockIdx.z * BM * ldc;
    int n0 = blockIdx.x * BN;

    __shared__ float As [BK][BM];
    __shared__ float Bs0[BK][BN];
    __shared__ float Bs1[BK][BN];

    int tid = threadIdx.x;
    int tx = tid & 15, ty = tid >> 4;

    float acc0[4][4] = {}, acc1[4][4] = {};

    for (int k0 = 0; k0 < Kdim; k0 += BK) {
        #pragma unroll
        for (int i = 0; i < 4; i++) {
            int idx = tid + i * 256;           // 1024 elems: 64 rows x 16 k
            int m = idx >> 4, k = idx & 15;
            As[k][m] = A[(size_t)m * lda + k0 + k];
        }
        #pragma unroll
        for (int i = 0; i < 4; i++) {
            int idx = tid + i * 256;           // 1024 elems: 16 k x 64 n
            int k = idx >> 6, n = idx & 63;
            const float* brow = B + (size_t)(k0 + k) * ldb + n0 + n;
            Bs0[k][n] = brow[0];
            Bs1[k][n] = brow[halfOff];
        }
        __syncthreads();
        #pragma unroll
        for (int k = 0; k < BK; k++) {
            float a[4], b0[4], b1[4];
            #pragma unroll
            for (int i = 0; i < 4; i++) a[i] = As[k][ty * 4 + i];
            #pragma unroll
            for (int j = 0; j < 4; j++) { b0[j] = Bs0[k][tx * 4 + j]; b1[j] = Bs1[k][tx * 4 + j]; }
            #pragma unroll
            for (int i = 0; i < 4; i++)
                #pragma unroll
                for (int j = 0; j < 4; j++) {
                    acc0[i][j] = fmaf(a[i], b0[j], acc0[i][j]);
                    acc1[i][j] = fmaf(a[i], b1[j], acc1[i][j]);
                }
        }
        __syncthreads();
    }

    #pragma unroll
    for (int i = 0; i < 4; i++) {
        int m = ty * 4 + i;
        #pragma unroll
        for (int j = 0; j < 4; j++) {
            int n = n0 + tx * 4 + j;
            float gate = acc0[i][j];
            float sil  = gate / (1.f + expf(-gate));
            C[(size_t)m * ldc + n] = sil * acc1[i][j];
        }
    }
}

// ---------------- Plain GEMM (expert down-proj & shared down-proj) ----------------
__global__ __launch_bounds__(256)
void gemm_kernel(const float* __restrict__ A0, int lda, size_t sAe,
                 const float* __restrict__ B0, int ldb, size_t sBe,
                 float* __restrict__ C0, int ldc, size_t sCe,
                 int Kdim, const int* __restrict__ cnt)
{
    int e = blockIdx.y;
    if (cnt) { if ((int)blockIdx.z * BM >= cnt[e]) return; }
    const float* A = A0 + (size_t)e * sAe + (size_t)blockIdx.z * BM * lda;
    const float* B = B0 + (size_t)e * sBe;
    float* C       = C0 + (size_t)e * sCe + (size_t)blockIdx.z * BM * ldc;
    int n0 = blockIdx.x * BN;

    __shared__ float As[BK][BM];
    __shared__ float Bs[BK][BN];

    int tid = threadIdx.x;
    int tx = tid & 15, ty = tid >> 4;

    float acc[4][4] = {};

    for (int k0 = 0; k0 < Kdim; k0 += BK) {
        #pragma unroll
        for (int i = 0; i < 4; i++) {
            int idx = tid + i * 256;
            int m = idx >> 4, k = idx & 15;
            As[k][m] = A[(size_t)m * lda + k0 + k];
        }
        #pragma unroll
        for (int i = 0; i < 4; i++) {
            int idx = tid + i * 256;
            int k = idx >> 6, n = idx & 63;
            Bs[k][n] = B[(size_t)(k0 + k) * ldb + n0 + n];
        }
        __syncthreads();
        #pragma unroll
        for (int k = 0; k < BK; k++) {
            float a[4], b[4];
            #pragma unroll
            for (int i = 0; i < 4; i++) a[i] = As[k][ty * 4 + i];
            #pragma unroll
            for (int j = 0; j < 4; j++) b[j] = Bs[k][tx * 4 + j];
            #pragma unroll
            for (int i = 0; i < 4; i++)
                #pragma unroll
                for (int j = 0; j < 4; j++)
                    acc[i][j] = fmaf(a[i], b[j], acc[i][j]);
        }
        __syncthreads();
    }

    #pragma unroll
    for (int i = 0; i < 4; i++) {
        int m = ty * 4 + i;
        #pragma unroll
        for (int j = 0; j < 4; j++)
            C[(size_t)m * ldc + n0 + tx * 4 + j] = acc[i][j];
    }
}

// ---------------- Combine: out = shared (already in out) + sum_k w*eo ----------------
__global__ void combine_kernel(float* __restrict__ out)
{
    int t = blockIdx.x;
    int h = threadIdx.x;          // 256 threads x float4 = 1024
    int   ids[TOPK], pos[TOPK];
    float w[TOPK];
    #pragma unroll
    for (int k = 0; k < TOPK; k++) {
        ids[k] = g_ids[t * TOPK + k];
        pos[k] = g_pos[t * TOPK + k];
        w[k]   = g_wts[t * TOPK + k];
    }
    float4* o4 = (float4*)(out + (size_t)t * HDIM);
    float4 acc = o4[h];
    #pragma unroll
    for (int k = 0; k < TOPK; k++) {
        if (pos[k] < CAP) {
            const float4* v4 = (const float4*)(g_eo + ((size_t)ids[k] * CAP + pos[k]) * HDIM);
            float4 v = v4[h];
            acc.x = fmaf(w[k], v.x, acc.x);
            acc.y = fmaf(w[k], v.y, acc.y);
            acc.z = fmaf(w[k], v.z, acc.z);
            acc.w = fmaf(w[k], v.w, acc.w);
        }
    }
    o4[h] = acc;
}

// ---------------- Launch ----------------
extern "C" void kernel_launch(void* const* d_in, const int* in_sizes, int n_in,
                              void* d_out, int out_size)
{
    const float* x      = (const float*)d_in[0];
    const float* gate_w = (const float*)d_in[1];
    const float* bias   = (const float*)d_in[2];
    const float* w13    = (const float*)d_in[3];
    const float* w2     = (const float*)d_in[4];
    const float* sw13   = (const float*)d_in[5];
    const float* sw2    = (const float*)d_in[6];
    float* out = (float*)d_out;

    float *buf, *act, *eo, *acts;
    int *cnt;
    cudaGetSymbolAddress((void**)&buf,  g_buf);
    cudaGetSymbolAddress((void**)&act,  g_act);
    cudaGetSymbolAddress((void**)&eo,   g_eo);
    cudaGetSymbolAddress((void**)&acts, g_acts);
    cudaGetSymbolAddress((void**)&cnt,  g_cnt);

    // routing
    gate_topk_kernel<<<T_TOK, 64>>>(x, gate_w, bias);
    zero_cnt_kernel<<<1, 64>>>();
    assign_kernel<<<(T_TOK * TOPK + 255) / 256, 256>>>();
    scatter_kernel<<<T_TOK * TOPK, 128>>>(x);

    // shared experts: up-proj + silu*mul -> g_acts
    gemm13_kernel<<<dim3(FSH / BN, 1, T_TOK / BM), 256>>>(
        x, HDIM, 0, sw13, 2 * FSH, 0, acts, FSH, 0,
        /*halfOff=*/FSH, /*K=*/HDIM, /*cnt=*/nullptr);

    // routed experts: up-proj + silu*mul -> g_act
    gemm13_kernel<<<dim3(FDIM / BN, NEXP, CAP / BM), 256>>>(
        buf, HDIM, (size_t)CAP * HDIM,
        w13, 2 * FDIM, (size_t)HDIM * 2 * FDIM,
        act, FDIM, (size_t)CAP * FDIM,
        /*halfOff=*/FDIM, /*K=*/HDIM, cnt);

    // routed down-proj -> g_eo
    gemm_kernel<<<dim3(HDIM / BN, NEXP, CAP / BM), 256>>>(
        act, FDIM, (size_t)CAP * FDIM,
        w2, HDIM, (size_t)FDIM * HDIM,
        eo, HDIM, (size_t)CAP * HDIM,
        /*K=*/FDIM, cnt);

    // shared down-proj -> out (base)
    gemm_kernel<<<dim3(HDIM / BN, 1, T_TOK / BM), 256>>>(
        acts, FSH, 0, sw2, HDIM, 0, out, HDIM, 0,
        /*K=*/FSH, /*cnt=*/nullptr);

    // weighted combine of routed outputs into out
    combine_kernel<<<T_TOK, 256>>>(out);
}

// round 3
// speedup vs baseline: 2.6043x; 2.6043x over previous
#include <cuda_runtime.h>
#include <cuda_fp16.h>
#include <cstdint>
#include <math.h>

// ---------------- Problem constants ----------------
#define T_TOK   1024
#define HDIM    1024
#define NEXP    64
#define TOPK    6
#define NGRP    8
#define TOPG    4
#define FDIM    512
#define FSH     1024
#define CAP     384
#define SCALE   2.5f

// ---------------- Device scratch ----------------
__device__ __align__(16) __half g_buf16 [(size_t)NEXP * CAP * HDIM];      // dispatch [E,CAP,H]
__device__ __align__(16) __half g_act16 [(size_t)NEXP * CAP * FDIM];      // act [E,CAP,F]
__device__ __align__(16) float  g_eo    [(size_t)NEXP * CAP * HDIM];      // expert out fp32
__device__ __align__(16) __half g_x16   [(size_t)T_TOK * HDIM];
__device__ __align__(16) __half g_acts16[(size_t)T_TOK * FSH];
__device__ __align__(16) __half g_w13h  [(size_t)NEXP * HDIM * 2 * FDIM]; // [E][H][2F]
__device__ __align__(16) __half g_w2h   [(size_t)NEXP * FDIM * HDIM];     // [E][F][H]
__device__ __align__(16) __half g_sw13h [(size_t)HDIM * 2 * FSH];         // [H][2FSH]
__device__ __align__(16) __half g_sw2h  [(size_t)FSH * HDIM];             // [FSH][H]
__device__ int   g_cnt[NEXP];
__device__ int   g_ids[T_TOK * TOPK];
__device__ int   g_pos[T_TOK * TOPK];
__device__ float g_wts[T_TOK * TOPK];

// ---------------- PTX helpers ----------------
static __device__ __forceinline__ uint32_t s2u(const void* p) {
    uint32_t a;
    asm("{ .reg .u64 t; cvta.to.shared.u64 t, %1; cvt.u32.u64 %0, t; }" : "=r"(a) : "l"(p));
    return a;
}
#define CPA16(dst, src) asm volatile("cp.async.cg.shared.global [%0], [%1], 16;" :: "r"(dst), "l"(src))
#define CP_COMMIT()     asm volatile("cp.async.commit_group;")
#define CP_WAIT1()      asm volatile("cp.async.wait_group 1;")
#define CP_WAIT0()      asm volatile("cp.async.wait_group 0;")

#define LDSM4(r, addr) \
    asm volatile("ldmatrix.sync.aligned.m8n8.x4.shared.b16 {%0,%1,%2,%3}, [%4];" \
        : "=r"((r)[0]), "=r"((r)[1]), "=r"((r)[2]), "=r"((r)[3]) : "r"(addr))
#define LDSM4T(r, addr) \
    asm volatile("ldmatrix.sync.aligned.m8n8.x4.trans.shared.b16 {%0,%1,%2,%3}, [%4];" \
        : "=r"((r)[0]), "=r"((r)[1]), "=r"((r)[2]), "=r"((r)[3]) : "r"(addr))

#define MMA16816(d, a, b0, b1) \
    asm volatile("mma.sync.aligned.m16n8k16.row.col.f32.f16.f16.f32 " \
        "{%0,%1,%2,%3}, {%4,%5,%6,%7}, {%8,%9}, {%0,%1,%2,%3};" \
        : "+f"((d)[0]), "+f"((d)[1]), "+f"((d)[2]), "+f"((d)[3]) \
        : "r"((a)[0]), "r"((a)[1]), "r"((a)[2]), "r"((a)[3]), "r"(b0), "r"(b1))

// SMEM tile geometry (halves)
#define LDA_S 40     // 32 k + 8 pad  (row stride 80B -> ldmatrix phase stride 5 mod 8)
#define LDB_S 136    // 128 n + 8 pad (row stride 272B -> 17 mod 8)
#define ABUF  (128 * LDA_S)
#define BBUF  (32 * LDB_S)

// ---------------- Gate + grouped top-k (exact fp32) ----------------
__global__ void gate_topk_kernel(const float* __restrict__ x,
                                 const float* __restrict__ gw,
                                 const float* __restrict__ bias)
{
    __shared__ float xs[HDIM];
    __shared__ float scores[NEXP];
    __shared__ float sc[NEXP];
    int t = blockIdx.x;
    for (int i = threadIdx.x; i < HDIM; i += blockDim.x) xs[i] = x[(size_t)t * HDIM + i];
    __syncthreads();
    int e = threadIdx.x;
    const float* g = gw + (size_t)e * HDIM;
    float acc = 0.f;
    #pragma unroll 8
    for (int i = 0; i < HDIM; i++) acc = fmaf(xs[i], g[i], acc);
    float s = 1.f / (1.f + expf(-acc));
    scores[e] = s;
    sc[e] = s + bias[e];
    __syncthreads();
    if (threadIdx.x == 0) {
        float gs[NGRP];
        for (int gi = 0; gi < NGRP; gi++) {
            float m1 = -1e30f, m2 = -1e30f;
            for (int j = 0; j < 8; j++) {
                float v = sc[gi * 8 + j];
                if (v > m1) { m2 = m1; m1 = v; } else if (v > m2) m2 = v;
            }
            gs[gi] = m1 + m2;
        }
        bool gsel[NGRP];
        for (int gi = 0; gi < NGRP; gi++) gsel[gi] = false;
        for (int r = 0; r < TOPG; r++) {
            int bi = -1; float bv = -1e30f;
            for (int gi = 0; gi < NGRP; gi++)
                if (!gsel[gi] && gs[gi] > bv) { bv = gs[gi]; bi = gi; }
            gsel[bi] = true;
        }
        float masked[NEXP];
        for (int i = 0; i < NEXP; i++) masked[i] = gsel[i >> 3] ? sc[i] : -1e30f;
        int id[TOPK]; float wsum = 0.f;
        for (int r = 0; r < TOPK; r++) {
            int bi = -1; float bv = -1e30f;
            for (int i = 0; i < NEXP; i++)
                if (masked[i] > bv) { bv = masked[i]; bi = i; }
            masked[bi] = -1e30f;
            id[r] = bi;
            wsum += scores[bi];
        }
        float inv = SCALE / wsum;
        for (int r = 0; r < TOPK; r++) {
            g_ids[t * TOPK + r] = id[r];
            g_wts[t * TOPK + r] = scores[id[r]] * inv;
        }
    }
}

__global__ void zero_cnt_kernel() { if (threadIdx.x < NEXP) g_cnt[threadIdx.x] = 0; }

__global__ void assign_kernel() {
    int i = blockIdx.x * blockDim.x + threadIdx.x;
    if (i < T_TOK * TOPK) g_pos[i] = atomicAdd(&g_cnt[g_ids[i]], 1);
}

__global__ void scatter16_kernel(const float* __restrict__ x) {
    int i = blockIdx.x;
    int p = g_pos[i];
    if (p >= CAP) return;
    int e = g_ids[i];
    int t = i / TOPK;
    const float4* src = (const float4*)(x + (size_t)t * HDIM);
    __half* dst = g_buf16 + ((size_t)e * CAP + p) * HDIM;
    for (int j = threadIdx.x; j < HDIM / 4; j += blockDim.x) {
        float4 v = src[j];
        __half2 a = __floats2half2_rn(v.x, v.y);
        __half2 b = __floats2half2_rn(v.z, v.w);
        uint2 u = make_uint2(*(uint32_t*)&a, *(uint32_t*)&b);
        *(uint2*)(dst + j * 4) = u;
    }
}

__global__ void conv16_kernel(const float* __restrict__ in, __half* __restrict__ out, int n4) {
    int i = blockIdx.x * blockDim.x + threadIdx.x;
    if (i < n4) {
        float4 v = ((const float4*)in)[i];
        __half2 a = __floats2half2_rn(v.x, v.y);
        __half2 b = __floats2half2_rn(v.z, v.w);
        uint2 u = make_uint2(*(uint32_t*)&a, *(uint32_t*)&b);
        *(uint2*)(out + (size_t)i * 4) = u;
    }
}

// ---------------- Fused up-proj + SiLU*Mul (mma.sync fp16) ----------------
// A [M][K] fp16 row-major (lda), B [K][2F] fp16 row-major (ldb): gate cols n0..n0+63,
// up cols halfOff+n0... C fp16 [M][F] (ldc): C[m][n0+j] = silu(gate)*up.
__global__ __launch_bounds__(256)
void gemm13_mma(const __half* __restrict__ A0, int lda, size_t sAe,
                const __half* __restrict__ B0, int ldb, size_t sBe, int halfOff,
                __half* __restrict__ C0, int ldc, size_t sCe,
                int Kdim, const int* __restrict__ cnt)
{
    __shared__ __align__(16) __half As[2 * ABUF];
    __shared__ __align__(16) __half Bs[2 * BBUF];

    int e = blockIdx.y;
    int m0 = blockIdx.z * 128;
    if (cnt && m0 >= cnt[e]) return;
    int n0 = blockIdx.x * 64;

    int tid = threadIdx.x;
    int warp = tid >> 5, lane = tid & 31;
    int mw = warp & 1, nw = warp >> 1;      // 2 x 4 warp grid: 64m x (16 gate + 16 up)

    const __half* A = A0 + (size_t)e * sAe + (size_t)m0 * lda;
    const __half* B = B0 + (size_t)e * sBe;
    uint32_t AsU = s2u(As), BsU = s2u(Bs);

    float accg[4][2][4] = {}, accu[4][2][4] = {};

    auto load_tiles = [&](int b, int k0) {
        // A: 128 rows x 32 halves, 2x16B per thread
        int ar = tid >> 1, ac = (tid & 1) * 2;
        const __half* Ag = A + (size_t)ar * lda + k0;
        uint32_t Ad = AsU + (uint32_t)(b * ABUF + ar * LDA_S) * 2;
        CPA16(Ad + ac * 16u, Ag + ac * 8);
        CPA16(Ad + (ac + 1) * 16u, Ag + (ac + 1) * 8);
        // B: 32 rows x (64 gate + 64 up) halves, 2x16B per thread
        int br = tid >> 3, cc = tid & 7;
        const __half* Bg = B + (size_t)(k0 + br) * ldb;
        uint32_t Bd = BsU + (uint32_t)(b * BBUF + br * LDB_S) * 2;
        CPA16(Bd + cc * 16u, Bg + n0 + cc * 8);
        CPA16(Bd + (64 + cc * 8) * 2u, Bg + halfOff + n0 + cc * 8);
    };

    int NC = Kdim / 32;
    load_tiles(0, 0);
    CP_COMMIT();
    for (int i = 0; i < NC; i++) {
        int b = i & 1;
        if (i + 1 < NC) { load_tiles(b ^ 1, (i + 1) * 32); CP_COMMIT(); CP_WAIT1(); }
        else CP_WAIT0();
        __syncthreads();

        uint32_t ab = AsU + (uint32_t)(b * ABUF) * 2;
        uint32_t bb = BsU + (uint32_t)(b * BBUF) * 2;
        #pragma unroll
        for (int ks = 0; ks < 32; ks += 16) {
            uint32_t af[4][4];
            #pragma unroll
            for (int mi = 0; mi < 4; mi++) {
                int r = mw * 64 + mi * 16 + (lane & 15);
                LDSM4(af[mi], ab + (uint32_t)(r * LDA_S + ks + (lane >> 4) * 8) * 2);
            }
            uint32_t bg[4], bu[4];
            int kr = ks + (lane & 15);
            LDSM4T(bg, bb + (uint32_t)(kr * LDB_S + nw * 16 + (lane >> 4) * 8) * 2);
            LDSM4T(bu, bb + (uint32_t)(kr * LDB_S + 64 + nw * 16 + (lane >> 4) * 8) * 2);
            #pragma unroll
            for (int mi = 0; mi < 4; mi++) {
                MMA16816(accg[mi][0], af[mi], bg[0], bg[1]);
                MMA16816(accg[mi][1], af[mi], bg[2], bg[3]);
                MMA16816(accu[mi][0], af[mi], bu[0], bu[1]);
                MMA16816(accu[mi][1], af[mi], bu[2], bu[3]);
            }
        }
        __syncthreads();
    }

    // epilogue: silu(gate)*up -> fp16
    int g = lane >> 2, c = lane & 3;
    #pragma unroll
    for (int mi = 0; mi < 4; mi++) {
        #pragma unroll
        for (int j = 0; j < 2; j++) {
            float* G = accg[mi][j];
            float* U = accu[mi][j];
            int col = n0 + nw * 16 + j * 8 + 2 * c;
            int r0 = m0 + mw * 64 + mi * 16 + g;
            float s0 = G[0] / (1.f + expf(-G[0])) * U[0];
            float s1 = G[1] / (1.f + expf(-G[1])) * U[1];
            float s2 = G[2] / (1.f + expf(-G[2])) * U[2];
            float s3 = G[3] / (1.f + expf(-G[3])) * U[3];
            __half2 h0 = __floats2half2_rn(s0, s1);
            __half2 h1 = __floats2half2_rn(s2, s3);
            *(__half2*)(C0 + (size_t)e * sCe + (size_t)r0 * ldc + col) = h0;
            *(__half2*)(C0 + (size_t)e * sCe + (size_t)(r0 + 8) * ldc + col) = h1;
        }
    }
}

// ---------------- Plain GEMM (mma.sync fp16, fp32 out) ----------------
__global__ __launch_bounds__(256)
void gemm2_mma(const __half* __restrict__ A0, int lda, size_t sAe,
               const __half* __restrict__ B0, int ldb, size_t sBe,
               float* __restrict__ C0, int ldc, size_t sCe,
               int Kdim, const int* __restrict__ cnt)
{
    __shared__ __align__(16) __half As[2 * ABUF];
    __shared__ __align__(16) __half Bs[2 * BBUF];

    int e = blockIdx.y;
    int m0 = blockIdx.z * 128;
    if (cnt && m0 >= cnt[e]) return;
    int n0 = blockIdx.x * 128;

    int tid = threadIdx.x;
    int warp = tid >> 5, lane = tid & 31;
    int mw = warp & 1, nw = warp >> 1;      // warp: 64m x 32n

    const __half* A = A0 + (size_t)e * sAe + (size_t)m0 * lda;
    const __half* B = B0 + (size_t)e * sBe;
    uint32_t AsU = s2u(As), BsU = s2u(Bs);

    float acc[4][4][4] = {};

    auto load_tiles = [&](int b, int k0) {
        int ar = tid >> 1, ac = (tid & 1) * 2;
        const __half* Ag = A + (size_t)ar * lda + k0;
        uint32_t Ad = AsU + (uint32_t)(b * ABUF + ar * LDA_S) * 2;
        CPA16(Ad + ac * 16u, Ag + ac * 8);
        CPA16(Ad + (ac + 1) * 16u, Ag + (ac + 1) * 8);
        int br = tid >> 3, cc = tid & 7;
        const __half* Bg = B + (size_t)(k0 + br) * ldb + n0;
        uint32_t Bd = BsU + (uint32_t)(b * BBUF + br * LDB_S) * 2;
        CPA16(Bd + cc * 16u, Bg + cc * 8);
        CPA16(Bd + (cc + 8) * 16u, Bg + (cc + 8) * 8);
    };

    int NC = Kdim / 32;
    load_tiles(0, 0);
    CP_COMMIT();
    for (int i = 0; i < NC; i++) {
        int b = i & 1;
        if (i + 1 < NC) { load_tiles(b ^ 1, (i + 1) * 32); CP_COMMIT(); CP_WAIT1(); }
        else CP_WAIT0();
        __syncthreads();

        uint32_t ab = AsU + (uint32_t)(b * ABUF) * 2;
        uint32_t bb = BsU + (uint32_t)(b * BBUF) * 2;
        #pragma unroll
        for (int ks = 0; ks < 32; ks += 16) {
            uint32_t af[4][4];
            #pragma unroll
            for (int mi = 0; mi < 4; mi++) {
                int r = mw * 64 + mi * 16 + (lane & 15);
                LDSM4(af[mi], ab + (uint32_t)(r * LDA_S + ks + (lane >> 4) * 8) * 2);
            }
            uint32_t bf0[4], bf1[4];
            int kr = ks + (lane & 15);
            LDSM4T(bf0, bb + (uint32_t)(kr * LDB_S + nw * 32 + (lane >> 4) * 8) * 2);
            LDSM4T(bf1, bb + (uint32_t)(kr * LDB_S + nw * 32 + 16 + (lane >> 4) * 8) * 2);
            #pragma unroll
            for (int mi = 0; mi < 4; mi++) {
                MMA16816(acc[mi][0], af[mi], bf0[0], bf0[1]);
                MMA16816(acc[mi][1], af[mi], bf0[2], bf0[3]);
                MMA16816(acc[mi][2], af[mi], bf1[0], bf1[1]);
                MMA16816(acc[mi][3], af[mi], bf1[2], bf1[3]);
            }
        }
        __syncthreads();
    }

    int g = lane >> 2, c = lane & 3;
    #pragma unroll
    for (int mi = 0; mi < 4; mi++) {
        #pragma unroll
        for (int j = 0; j < 4; j++) {
            float* D = acc[mi][j];
            int col = n0 + nw * 32 + j * 8 + 2 * c;
            int r0 = m0 + mw * 64 + mi * 16 + g;
            float* Cb = C0 + (size_t)e * sCe;
            *(float2*)(Cb + (size_t)r0 * ldc + col) = make_float2(D[0], D[1]);
            *(float2*)(Cb + (size_t)(r0 + 8) * ldc + col) = make_float2(D[2], D[3]);
        }
    }
}

// ---------------- Combine ----------------
__global__ void combine_kernel(float* __restrict__ out) {
    int t = blockIdx.x;
    int h = threadIdx.x;
    int ids[TOPK], pos[TOPK]; float w[TOPK];
    #pragma unroll
    for (int k = 0; k < TOPK; k++) {
        ids[k] = g_ids[t * TOPK + k];
        pos[k] = g_pos[t * TOPK + k];
        w[k]   = g_wts[t * TOPK + k];
    }
    float4* o4 = (float4*)(out + (size_t)t * HDIM);
    float4 acc = o4[h];
    #pragma unroll
    for (int k = 0; k < TOPK; k++) {
        if (pos[k] < CAP) {
            const float4* v4 = (const float4*)(g_eo + ((size_t)ids[k] * CAP + pos[k]) * HDIM);
            float4 v = v4[h];
            acc.x = fmaf(w[k], v.x, acc.x);
            acc.y = fmaf(w[k], v.y, acc.y);
            acc.z = fmaf(w[k], v.z, acc.z);
            acc.w = fmaf(w[k], v.w, acc.w);
        }
    }
    o4[h] = acc;
}

// ---------------- Launch ----------------
extern "C" void kernel_launch(void* const* d_in, const int* in_sizes, int n_in,
                              void* d_out, int out_size)
{
    const float* x      = (const float*)d_in[0];
    const float* gate_w = (const float*)d_in[1];
    const float* bias   = (const float*)d_in[2];
    const float* w13    = (const float*)d_in[3];
    const float* w2     = (const float*)d_in[4];
    const float* sw13   = (const float*)d_in[5];
    const float* sw2    = (const float*)d_in[6];
    float* out = (float*)d_out;

    __half *buf16, *act16, *x16, *acts16, *w13h, *w2h, *sw13h, *sw2h;
    float* eo; int* cnt;
    cudaGetSymbolAddress((void**)&buf16,  g_buf16);
    cudaGetSymbolAddress((void**)&act16,  g_act16);
    cudaGetSymbolAddress((void**)&eo,     g_eo);
    cudaGetSymbolAddress((void**)&x16,    g_x16);
    cudaGetSymbolAddress((void**)&acts16, g_acts16);
    cudaGetSymbolAddress((void**)&w13h,   g_w13h);
    cudaGetSymbolAddress((void**)&w2h,    g_w2h);
    cudaGetSymbolAddress((void**)&sw13h,  g_sw13h);
    cudaGetSymbolAddress((void**)&sw2h,   g_sw2h);
    cudaGetSymbolAddress((void**)&cnt,    g_cnt);

    // routing (exact fp32)
    gate_topk_kernel<<<T_TOK, 64>>>(x, gate_w, bias);
    zero_cnt_kernel<<<1, 64>>>();
    assign_kernel<<<(T_TOK * TOPK + 255) / 256, 256>>>();
    scatter16_kernel<<<T_TOK * TOPK, 128>>>(x);

    // fp32 -> fp16 converts (no transpose needed for mma.sync B operand)
    conv16_kernel<<<(T_TOK * HDIM / 4 + 255) / 256, 256>>>(x, x16, T_TOK * HDIM / 4);
    {
        int n4 = NEXP * HDIM * 2 * FDIM / 4;
        conv16_kernel<<<(n4 + 255) / 256, 256>>>(w13, w13h, n4);
    }
    {
        int n4 = NEXP * FDIM * HDIM / 4;
        conv16_kernel<<<(n4 + 255) / 256, 256>>>(w2, w2h, n4);
    }
    {
        int n4 = HDIM * 2 * FSH / 4;
        conv16_kernel<<<(n4 + 255) / 256, 256>>>(sw13, sw13h, n4);
    }
    {
        int n4 = FSH * HDIM / 4;
        conv16_kernel<<<(n4 + 255) / 256, 256>>>(sw2, sw2h, n4);
    }

    // routed up-proj + SiLU*Mul -> act16   (B=[H][2F], gate n, up F+n)
    gemm13_mma<<<dim3(FDIM / 64, NEXP, CAP / 128), 256>>>(
        buf16, HDIM, (size_t)CAP * HDIM,
        w13h, 2 * FDIM, (size_t)HDIM * 2 * FDIM, FDIM,
        act16, FDIM, (size_t)CAP * FDIM,
        HDIM, cnt);

    // shared up-proj + SiLU*Mul -> acts16  (B=[H][2FSH])
    gemm13_mma<<<dim3(FSH / 64, 1, T_TOK / 128), 256>>>(
        x16, HDIM, 0,
        sw13h, 2 * FSH, 0, FSH,
        acts16, FSH, 0,
        HDIM, nullptr);

    // routed down-proj -> eo (fp32)
    gemm2_mma<<<dim3(HDIM / 128, NEXP, CAP / 128), 256>>>(
        act16, FDIM, (size_t)CAP * FDIM,
        w2h, HDIM, (size_t)FDIM * HDIM,
        eo, HDIM, (size_t)CAP * HDIM,
        FDIM, cnt);

    // shared down-proj -> out (fp32 base)
    gemm2_mma<<<dim3(HDIM / 128, 1, T_TOK / 128), 256>>>(
        acts16, FSH, 0,
        sw2h, HDIM, 0,
        out, HDIM, 0,
        FSH, nullptr);

    combine_kernel<<<T_TOK, 256>>>(out);
}